// round 11
// baseline (speedup 1.0000x reference)
#include <cuda_runtime.h>
#include <cuda_bf16.h>
#include <cstdint>

// ---------------- problem shape ----------------
#define TOK   32768
#define HDIM  4096
#define NE    64
#define BM    128            // tokens per CTA
#define KI    64             // k per iteration
#define KT    32             // tensor k per iteration (2 ksteps of 16)
#define KF    32             // fma k per iteration
#define NIT   64             // HDIM / KI
#define NT    256            // threads (8 warps)
#define TAU   1e-4f

// smem per buffer:
//  XH[128 tok][80B]   @ 0       (10240)   bf16 high plane, pad-80 rows
//  XL[128 tok][80B]   @ 10240   (10240)   bf16 low plane
//  W3 h+l planes      @ 20480   (10240)   2 x 64 e x 80B
//  XF[32 k][544B]     @ 30720   (17408)   fp32 x transposed [k][t], pad-544 rows
//  WF[32 k][256B]     @ 48128   (8192)    fp32 w [k][e]
#define XH_OFF 0
#define XL_OFF 10240
#define W3_OFF 20480
#define XF_OFF 30720
#define WF_OFF 48128
#define BUFB   56320
#define SMEMB  (2 * BUFB)    // 112640 per CTA -> 2 CTAs/SM

// ---------------- device globals ----------------
__device__ unsigned char g_w3[NIT * 10240];  // [iter][plane h/l][e 64][80B rows]
__device__ float g_wf[NIT * 32 * 64];        // [iter][k 32][e 64] fp32
__device__ float g_wtr[HDIM * NE];           // [k][e] fp32 (cleanup table)
__device__ int g_flag_count;
__device__ int g_flag_list[TOK];

// ---------------- helpers ----------------
__device__ __forceinline__ uint32_t s2u(const void* p) {
    uint32_t a;
    asm("{ .reg .u64 t; cvta.to.shared.u64 t, %1; cvt.u32.u64 %0, t; }" : "=r"(a) : "l"(p));
    return a;
}
__device__ __forceinline__ uint32_t cvt2bf(float f1, float f0) {
    uint32_t d;
    asm("cvt.rn.bf16x2.f32 %0, %1, %2;" : "=r"(d) : "f"(f1), "f"(f0));
    return d;
}
__device__ __forceinline__ void splitpair(float f0, float f1, uint32_t& h, uint32_t& l) {
    h = cvt2bf(f1, f0);
    float h0 = __uint_as_float(h << 16);
    float h1 = __uint_as_float(h & 0xFFFF0000u);
    l = cvt2bf(f1 - h1, f0 - h0);
}
__device__ __forceinline__ void ldsm4(uint32_t* r, uint32_t addr) {
    asm volatile("ldmatrix.sync.aligned.m8n8.x4.shared.b16 {%0,%1,%2,%3}, [%4];"
                 : "=r"(r[0]), "=r"(r[1]), "=r"(r[2]), "=r"(r[3]) : "r"(addr));
}
__device__ __forceinline__ void mma16816(float* c, const uint32_t* a,
                                         uint32_t b0, uint32_t b1) {
    asm("mma.sync.aligned.m16n8k16.row.col.f32.bf16.bf16.f32 "
        "{%0,%1,%2,%3}, {%4,%5,%6,%7}, {%8,%9}, {%0,%1,%2,%3};"
        : "+f"(c[0]), "+f"(c[1]), "+f"(c[2]), "+f"(c[3])
        : "r"(a[0]), "r"(a[1]), "r"(a[2]), "r"(a[3]), "r"(b0), "r"(b1));
}
#define FMA2(d, a, b) \
    asm("fma.rn.f32x2 %0, %1, %2, %0;" : "+l"(d) : "l"(a), "l"(b))
#define DUP2(d, s) \
    asm("mov.b64 %0, {%1, %1};" : "=l"(d) : "f"(s))
#define UNPK2(lo, hi, p) \
    asm("mov.b64 {%0, %1}, %2;" : "=f"(lo), "=f"(hi) : "l"(p))
__device__ __forceinline__ void cpasync16(uint32_t dst, const void* src) {
    asm volatile("cp.async.ca.shared.global [%0], [%1], 16;" :: "r"(dst), "l"(src));
}
#define CP_COMMIT() asm volatile("cp.async.commit_group;" ::: "memory")
#define CP_WAIT0()  asm volatile("cp.async.wait_group 0;" ::: "memory")

// ---------------- prep kernels ----------------
// bf16 h/l planes for k [i*64, i*64+32), expert rows padded to 80B
__global__ void prep_w3(const float* __restrict__ W) {
    int id = blockIdx.x * 256 + threadIdx.x;   // NIT*NE = 4096
    if (id == 0) g_flag_count = 0;
    if (id >= NIT * NE) return;
    int i = id >> 6, e = id & 63;
    const float* src = W + (size_t)e * HDIM + i * KI;
    unsigned char* dh = g_w3 + (size_t)i * 10240 + e * 80;
    unsigned char* dl = dh + 5120;
#pragma unroll
    for (int kp = 0; kp < 16; ++kp) {          // 32 k = 16 pairs
        uint32_t h, l;
        splitpair(src[2 * kp], src[2 * kp + 1], h, l);
        *(uint32_t*)(dh + kp * 4) = h;
        *(uint32_t*)(dl + kp * 4) = l;
    }
}
// fp32 [k][e] for k [i*64+32, i*64+64)
__global__ void prep_wf(const float* __restrict__ W) {
    int id = blockIdx.x * 256 + threadIdx.x;   // NIT*32*64 = 131072
    if (id >= NIT * 32 * 64) return;
    int i = id >> 11, r = id & 2047;
    int k = r >> 6, e = r & 63;
    g_wf[id] = W[(size_t)e * HDIM + i * KI + KT + k];
}
// full transposed fp32 table for cleanup
__global__ void prep_wtr(const float* __restrict__ W) {
    int id = blockIdx.x * 256 + threadIdx.x;   // 262144
    if (id >= HDIM * NE) return;
    int k = id >> 6, e = id & 63;
    g_wtr[id] = W[(size_t)e * HDIM + k];
}

// ---------------- main: hybrid tensor(K/2) + FFMA2(K/2) ----------------
__global__ void __launch_bounds__(NT, 2)
moe_gate_hybrid(const float* __restrict__ X, float* __restrict__ out) {
    extern __shared__ __align__(16) char smc[];
    const uint32_t sbase = s2u(smc);

    const int tid  = threadIdx.x;
    const int lane = tid & 31, wid = tid >> 5;     // 8 warps
    const int lrow = lane & 15, lkh = lane >> 4;
    const int tok0 = blockIdx.x * BM;
    const float* Xg = X + (size_t)tok0 * HDIM;

    // tensor ldmatrix lane addresses (pad-80 rows; kstep = +32B plain add)
    const uint32_t aH = sbase + XH_OFF + (uint32_t)((wid * 16 + lrow) * 80 + lkh * 16);
    const uint32_t aL = aH + (XL_OFF - XH_OFF);
    uint32_t bH[4];
#pragma unroll
    for (int np = 0; np < 4; ++np)
        bH[np] = sbase + W3_OFF + (uint32_t)((np * 16 + lrow) * 80 + lkh * 16);

    // fma thread tile: tokens t0..t0+3, experts eg*8..+7
    const int eg = lane & 7;
    const int tg = (lane >> 3) & 3;
    const int t0 = wid * 16 + tg * 4;

    float accT[8][4];
    uint64_t accF[4][4];
#pragma unroll
    for (int nt = 0; nt < 8; ++nt)
#pragma unroll
        for (int q = 0; q < 4; ++q) accT[nt][q] = 0.0f;
#pragma unroll
    for (int p = 0; p < 4; ++p)
#pragma unroll
        for (int t = 0; t < 4; ++t) accF[p][t] = 0ull;

    float4 xa[4];   // tensor X staging: 128 tok x 32 k = 1024 float4 / 256 thr
    float4 xf4[4];  // fma X staging:    128 tok x 32 k

#define LDG_XT(ii)                                                              \
    {                                                                           \
        _Pragma("unroll")                                                       \
        for (int it = 0; it < 4; ++it) {                                        \
            int f = it * NT + tid;                                              \
            int row = f >> 3, q = f & 7;                                        \
            xa[it] = *(const float4*)(Xg + (size_t)row * HDIM + (ii) * KI + q * 4); \
        }                                                                       \
    }

#define LDG_XF(ii)                                                              \
    {                                                                           \
        _Pragma("unroll")                                                       \
        for (int it = 0; it < 4; ++it) {                                        \
            int f = it * NT + tid;                                              \
            int row = f >> 3, q = f & 7;                                        \
            xf4[it] = *(const float4*)(Xg + (size_t)row * HDIM + (ii) * KI + KT + q * 4); \
        }                                                                       \
    }

#define CVT_XT(bufo)                                                            \
    {                                                                           \
        _Pragma("unroll")                                                       \
        for (int it = 0; it < 4; ++it) {                                        \
            int f = it * NT + tid;                                              \
            int row = f >> 3, q = f & 7;                                        \
            uint32_t h0, l0, h1, l1;                                            \
            splitpair(xa[it].x, xa[it].y, h0, l0);                              \
            splitpair(xa[it].z, xa[it].w, h1, l1);                              \
            char* base = smc + (bufo) + row * 80 + q * 8;                       \
            *(uint2*)(base + XH_OFF) = make_uint2(h0, h1);                      \
            *(uint2*)(base + XL_OFF) = make_uint2(l0, l1);                      \
        }                                                                       \
    }

#define STS_XF(bufo)                                                            \
    {                                                                           \
        _Pragma("unroll")                                                       \
        for (int it = 0; it < 4; ++it) {                                        \
            int f = it * NT + tid;                                              \
            int row = f >> 3, q = f & 7;                                        \
            float* d = (float*)(smc + (bufo) + XF_OFF);                         \
            d[(q * 4 + 0) * 136 + row] = xf4[it].x;                             \
            d[(q * 4 + 1) * 136 + row] = xf4[it].y;                             \
            d[(q * 4 + 2) * 136 + row] = xf4[it].z;                             \
            d[(q * 4 + 3) * 136 + row] = xf4[it].w;                             \
        }                                                                       \
    }

#define CP_ALL(ii, bufo)                                                        \
    {                                                                           \
        const char* ws = (const char*)g_w3 + (size_t)(ii) * 10240;              \
        _Pragma("unroll")                                                       \
        for (int q = 0; q < 3; ++q) {                                           \
            int idx = q * NT + tid;                                             \
            if (idx < 640)                                                      \
                cpasync16(sbase + (bufo) + W3_OFF + idx * 16, ws + idx * 16);   \
        }                                                                       \
        const char* wf = (const char*)g_wf + (size_t)(ii) * 8192;               \
        _Pragma("unroll")                                                       \
        for (int q = 0; q < 2; ++q) {                                           \
            int idx = q * NT + tid;                                             \
            cpasync16(sbase + (bufo) + WF_OFF + idx * 16, wf + idx * 16);       \
        }                                                                       \
        CP_COMMIT();                                                            \
    }

    // ---- stage iteration 0 ----
    LDG_XT(0);
    LDG_XF(0);
    CP_ALL(0, 0);
    CVT_XT(0);
    STS_XF(0);
    CP_WAIT0();
    __syncthreads();

    for (int i = 0; i < NIT; ++i) {
        const uint32_t bufR = (uint32_t)(i & 1) * BUFB;
        const uint32_t bufW = (uint32_t)((i + 1) & 1) * BUFB;
        const bool more = (i + 1 < NIT);

        if (more) {
            LDG_XT(i + 1);
            LDG_XF(i + 1);
            CP_ALL(i + 1, bufW);
        }

        // ---- tensor section: 2 ksteps x 4 np x 2 sub x 3 passes = 48 MMAs ----
#pragma unroll
        for (int ks = 0; ks < 2; ++ks) {
            const uint32_t ko = (uint32_t)(ks * 32);
            uint32_t Ah[4], Al[4];
            ldsm4(Ah, aH + bufR + ko);
            ldsm4(Al, aL + bufR + ko);
#pragma unroll
            for (int np = 0; np < 4; ++np) {
                uint32_t Bh[4], Bl[4];
                ldsm4(Bh, bH[np] + bufR + ko);
                ldsm4(Bl, bH[np] + bufR + ko + 5120);
#pragma unroll
                for (int sub = 0; sub < 2; ++sub) {
                    float* cc = accT[np * 2 + sub];
                    mma16816(cc, Ah, Bh[sub], Bh[2 + sub]);   // h*h
                    mma16816(cc, Ah, Bl[sub], Bl[2 + sub]);   // h*l
                    mma16816(cc, Al, Bh[sub], Bh[2 + sub]);   // l*h
                }
            }
        }

        // ---- fma section: 32 kk exact fp32 on the FMA pipe ----
        {
            const char* xf = smc + bufR + XF_OFF;
            const char* wf = smc + bufR + WF_OFF;
#pragma unroll 8
            for (int kk = 0; kk < KF; ++kk) {
                float4 xv = *(const float4*)(xf + kk * 544 + t0 * 4);
                uint64_t xd[4];
                DUP2(xd[0], xv.x);
                DUP2(xd[1], xv.y);
                DUP2(xd[2], xv.z);
                DUP2(xd[3], xv.w);
                const char* wrow = wf + kk * 256 + eg * 32;
                ulonglong2 wA = *(const ulonglong2*)(wrow);       // expert pairs (0,1),(2,3)
                ulonglong2 wB = *(const ulonglong2*)(wrow + 16);  // (4,5),(6,7)
#pragma unroll
                for (int t = 0; t < 4; ++t) {
                    FMA2(accF[0][t], xd[t], wA.x);
                    FMA2(accF[1][t], xd[t], wA.y);
                    FMA2(accF[2][t], xd[t], wB.x);
                    FMA2(accF[3][t], xd[t], wB.y);
                }
            }
        }

        if (more) {
            CVT_XT(bufW);
            STS_XF(bufW);
            CP_WAIT0();
        }
        __syncthreads();
    }

    // ---- merge: tensor fragments write lg, then fma accs add in ----
    float* lg = (float*)smc;
    const int g = lane >> 2, tig = lane & 3;
#pragma unroll
    for (int nt = 0; nt < 8; ++nt) {
        int r0 = wid * 16 + g;
        int e0 = nt * 8 + tig * 2;
        lg[r0 * 66 + e0]           = accT[nt][0];
        lg[r0 * 66 + e0 + 1]       = accT[nt][1];
        lg[(r0 + 8) * 66 + e0]     = accT[nt][2];
        lg[(r0 + 8) * 66 + e0 + 1] = accT[nt][3];
    }
    __syncthreads();
#pragma unroll
    for (int p = 0; p < 4; ++p) {
        int e = eg * 8 + 2 * p;
#pragma unroll
        for (int t = 0; t < 4; ++t) {
            float lo, hi;
            UNPK2(lo, hi, accF[p][t]);
            lg[(t0 + t) * 66 + e]     += lo;
            lg[(t0 + t) * 66 + e + 1] += hi;
        }
    }
    __syncthreads();

    // ---- per-token softmax + top-3 + near-tie flag (threads 0..127) ----
    if (tid < BM) {
        const int t = tid;
        const float* row = lg + t * 66;
        float mx = row[0];
#pragma unroll 8
        for (int e = 1; e < NE; ++e) mx = fmaxf(mx, row[e]);
        float sum = 0.0f;
        float s1 = -3.4e38f, s2 = -3.4e38f, s3 = -3.4e38f;
        int i1 = 0, i2 = 0;
#pragma unroll 8
        for (int e = 0; e < NE; ++e) {
            float l = row[e];
            sum += expf(l - mx);
            if (l > s1)      { s3 = s2; s2 = s1; i2 = i1; s1 = l; i1 = e; }
            else if (l > s2) { s3 = s2; s2 = l; i2 = e; }
            else if (l > s3) { s3 = l; }
        }
        float inv = 1.0f / sum;
        int gt = tok0 + t;
        out[2 * gt]               = (float)i1;
        out[2 * gt + 1]           = (float)i2;
        out[2 * TOK + 2 * gt]     = expf(s1 - mx) * inv;
        out[2 * TOK + 2 * gt + 1] = expf(s2 - mx) * inv;
        if ((s1 - s2 < TAU) || (s2 - s3 < TAU)) {
            int sl = atomicAdd(&g_flag_count, 1);
            if (sl < TOK) g_flag_list[sl] = gt;
        }
    }
}

// ---------------- cleanup v2: batched (16 tokens/block-iter), coalesced ----------------
__global__ void cleanup_kernel(const float* __restrict__ X, float* __restrict__ out) {
    __shared__ __align__(16) float xs[16 * 256];   // chunk: 16 tok x 256 k
    __shared__ double lgb[16 * 66];
    __shared__ int tks[16];
    const int tid = threadIdx.x;
    int nf = g_flag_count;
    if (nf > TOK) nf = TOK;
    int nbat = (nf + 15) >> 4;

    for (int j = blockIdx.x; j < nbat; j += gridDim.x) {
        if (tid < 16) {
            int idx = j * 16 + tid;
            tks[tid] = (idx < nf) ? g_flag_list[idx] : -1;
        }
        __syncthreads();

        const int e  = tid & 63;
        const int tq = tid >> 6;          // token slots tq, tq+4, tq+8, tq+12
        double accd[4] = {0.0, 0.0, 0.0, 0.0};

        for (int kc = 0; kc < 16; ++kc) {
            // stage X chunk (coalesced)
#pragma unroll
            for (int it = 0; it < 4; ++it) {
                int f = it * 256 + tid;
                int r = f >> 6, c = (f & 63) * 4;
                int t = tks[r];
                float4 v = (t >= 0)
                    ? *(const float4*)(X + (size_t)t * HDIM + kc * 256 + c)
                    : make_float4(0.f, 0.f, 0.f, 0.f);
                *(float4*)(xs + r * 256 + c) = v;
            }
            __syncthreads();
            // fp32 chunk partials (coalesced W), fold into double
            float tp[4] = {0.f, 0.f, 0.f, 0.f};
            const float* wt = g_wtr + (size_t)(kc * 256) * 64 + e;
#pragma unroll 4
            for (int k = 0; k < 256; ++k) {
                float w = wt[k * 64];
                tp[0] = fmaf(xs[(tq + 0) * 256 + k], w, tp[0]);
                tp[1] = fmaf(xs[(tq + 4) * 256 + k], w, tp[1]);
                tp[2] = fmaf(xs[(tq + 8) * 256 + k], w, tp[2]);
                tp[3] = fmaf(xs[(tq + 12) * 256 + k], w, tp[3]);
            }
#pragma unroll
            for (int m = 0; m < 4; ++m) accd[m] += (double)tp[m];
            __syncthreads();
        }

#pragma unroll
        for (int m = 0; m < 4; ++m) lgb[(tq + 4 * m) * 66 + e] = accd[m];
        __syncthreads();

        if (tid < 16 && tks[tid] >= 0) {
            int t = tks[tid];
            const double* row = lgb + tid * 66;
            double mx = row[0];
            for (int q = 1; q < NE; ++q) if (row[q] > mx) mx = row[q];
            double sum = 0.0;
            double s1 = -1e300, s2 = -1e300;
            int i1 = 0, i2 = 0;
            for (int q = 0; q < NE; ++q) {
                double l = row[q];
                sum += exp(l - mx);
                if (l > s1)      { s2 = s1; i2 = i1; s1 = l; i1 = q; }
                else if (l > s2) { s2 = l; i2 = q; }
            }
            double inv = 1.0 / sum;
            out[2 * t]               = (float)i1;
            out[2 * t + 1]           = (float)i2;
            out[2 * TOK + 2 * t]     = (float)(exp(s1 - mx) * inv);
            out[2 * TOK + 2 * t + 1] = (float)(exp(s2 - mx) * inv);
        }
        __syncthreads();
    }
}

// ---------------- launch ----------------
extern "C" void kernel_launch(void* const* d_in, const int* in_sizes, int n_in,
                              void* d_out, int out_size) {
    const float* X = (const float*)d_in[0];
    const float* W = (const float*)d_in[1];
    float* out = (float*)d_out;

    static bool once = []() {
        cudaFuncSetAttribute(moe_gate_hybrid, cudaFuncAttributeMaxDynamicSharedMemorySize,
                             SMEMB);
        return true;
    }();
    (void)once;

    prep_w3<<<16, 256>>>(W);
    prep_wf<<<512, 256>>>(W);
    prep_wtr<<<1024, 256>>>(W);
    moe_gate_hybrid<<<TOK / BM, NT, SMEMB>>>(X, out);
    cleanup_kernel<<<256, 256>>>(X, out);
}

// round 12
// speedup vs baseline: 2.2322x; 2.2322x over previous
#include <cuda_runtime.h>
#include <cuda_bf16.h>
#include <cstdint>

// ---------------- problem shape ----------------
#define TOK   32768
#define HDIM  4096
#define NE    64
#define BM    128            // tokens per CTA
#define KI    64             // k per iteration
#define KT    32             // tensor k per iteration (2 ksteps of 16)
#define KF    32             // fma k per iteration
#define NIT   64             // HDIM / KI
#define NT    256            // threads (8 warps)
#define TAU   1e-4f

// smem per buffer:
//  XH[128 tok][80B]   @ 0       (10240)   bf16 high plane, pad-80 rows
//  XL[128 tok][80B]   @ 10240   (10240)   bf16 low plane
//  W3 h+l planes      @ 20480   (10240)   2 x 64 e x 80B
//  XF[128 tok][136B]  @ 30720   (17408)   fp32 x [t][k], pad-136 rows (bank-clean)
//  WF[32 k][256B]     @ 48128   (8192)    fp32 w [k][e] (duplicated pairs NOT needed)
#define XH_OFF 0
#define XL_OFF 10240
#define W3_OFF 20480
#define XF_OFF 30720
#define WF_OFF 48128
#define BUFB   56320
#define SMEMB  (2 * BUFB)    // 112640 per CTA -> 2 CTAs/SM

// ---------------- device globals ----------------
__device__ unsigned char g_w3[NIT * 10240];  // [iter][plane h/l][e 64][80B rows]
__device__ float g_wf[NIT * 32 * 64];        // [iter][k 32][e 64] fp32
__device__ int g_flag_count;
__device__ int g_flag_tok[TOK];
__device__ unsigned int g_flag_pk[TOK];      // packed top-4 expert ids
__device__ float g_flag_mx[TOK];
__device__ float g_flag_sum[TOK];

// ---------------- helpers ----------------
__device__ __forceinline__ uint32_t s2u(const void* p) {
    uint32_t a;
    asm("{ .reg .u64 t; cvta.to.shared.u64 t, %1; cvt.u32.u64 %0, t; }" : "=r"(a) : "l"(p));
    return a;
}
__device__ __forceinline__ uint32_t cvt2bf(float f1, float f0) {
    uint32_t d;
    asm("cvt.rn.bf16x2.f32 %0, %1, %2;" : "=r"(d) : "f"(f1), "f"(f0));
    return d;
}
__device__ __forceinline__ void splitpair(float f0, float f1, uint32_t& h, uint32_t& l) {
    h = cvt2bf(f1, f0);
    float h0 = __uint_as_float(h << 16);
    float h1 = __uint_as_float(h & 0xFFFF0000u);
    l = cvt2bf(f1 - h1, f0 - h0);
}
__device__ __forceinline__ void ldsm4(uint32_t* r, uint32_t addr) {
    asm volatile("ldmatrix.sync.aligned.m8n8.x4.shared.b16 {%0,%1,%2,%3}, [%4];"
                 : "=r"(r[0]), "=r"(r[1]), "=r"(r[2]), "=r"(r[3]) : "r"(addr));
}
__device__ __forceinline__ void mma16816(float* c, const uint32_t* a,
                                         uint32_t b0, uint32_t b1) {
    asm("mma.sync.aligned.m16n8k16.row.col.f32.bf16.bf16.f32 "
        "{%0,%1,%2,%3}, {%4,%5,%6,%7}, {%8,%9}, {%0,%1,%2,%3};"
        : "+f"(c[0]), "+f"(c[1]), "+f"(c[2]), "+f"(c[3])
        : "r"(a[0]), "r"(a[1]), "r"(a[2]), "r"(a[3]), "r"(b0), "r"(b1));
}
#define FMA2(d, a, b) \
    asm("fma.rn.f32x2 %0, %1, %2, %0;" : "+l"(d) : "l"(a), "l"(b))
#define DUP2(d, s) \
    asm("mov.b64 %0, {%1, %1};" : "=l"(d) : "f"(s))
#define UNPK2(lo, hi, p) \
    asm("mov.b64 {%0, %1}, %2;" : "=f"(lo), "=f"(hi) : "l"(p))
__device__ __forceinline__ void cpasync16(uint32_t dst, const void* src) {
    asm volatile("cp.async.ca.shared.global [%0], [%1], 16;" :: "r"(dst), "l"(src));
}
__device__ __forceinline__ void cpasync8(uint32_t dst, const void* src) {
    asm volatile("cp.async.ca.shared.global [%0], [%1], 8;" :: "r"(dst), "l"(src));
}
#define CP_COMMIT() asm volatile("cp.async.commit_group;" ::: "memory")
#define CP_WAIT0()  asm volatile("cp.async.wait_group 0;" ::: "memory")

// ---------------- prep kernels ----------------
__global__ void prep_w3(const float* __restrict__ W) {
    int id = blockIdx.x * 256 + threadIdx.x;   // NIT*NE = 4096
    if (id == 0) g_flag_count = 0;
    if (id >= NIT * NE) return;
    int i = id >> 6, e = id & 63;
    const float* src = W + (size_t)e * HDIM + i * KI;
    unsigned char* dh = g_w3 + (size_t)i * 10240 + e * 80;
    unsigned char* dl = dh + 5120;
#pragma unroll
    for (int kp = 0; kp < 16; ++kp) {          // 32 k = 16 pairs
        uint32_t h, l;
        splitpair(src[2 * kp], src[2 * kp + 1], h, l);
        *(uint32_t*)(dh + kp * 4) = h;
        *(uint32_t*)(dl + kp * 4) = l;
    }
}
__global__ void prep_wf(const float* __restrict__ W) {
    int id = blockIdx.x * 256 + threadIdx.x;   // NIT*32*64 = 131072
    if (id >= NIT * 32 * 64) return;
    int i = id >> 11, r = id & 2047;
    int k = r >> 6, e = r & 63;
    g_wf[id] = W[(size_t)e * HDIM + i * KI + KT + k];
}

// ---------------- main: hybrid tensor(K/2) + FFMA2(K/2) ----------------
__global__ void __launch_bounds__(NT, 2)
moe_gate_hybrid(const float* __restrict__ X, float* __restrict__ out) {
    extern __shared__ __align__(16) char smc[];
    const uint32_t sbase = s2u(smc);

    const int tid  = threadIdx.x;
    const int lane = tid & 31, wid = tid >> 5;     // 8 warps
    const int lrow = lane & 15, lkh = lane >> 4;
    const int tok0 = blockIdx.x * BM;
    const float* Xg = X + (size_t)tok0 * HDIM;

    // tensor ldmatrix lane addresses (pad-80 rows; kstep = +32B plain add)
    const uint32_t aH = sbase + XH_OFF + (uint32_t)((wid * 16 + lrow) * 80 + lkh * 16);
    const uint32_t aL = aH + (XL_OFF - XH_OFF);
    uint32_t bH[4];
#pragma unroll
    for (int np = 0; np < 4; ++np)
        bH[np] = sbase + W3_OFF + (uint32_t)((np * 16 + lrow) * 80 + lkh * 16);

    // fma thread tile: tokens t0..t0+3, experts eg*8..+7
    const int eg = lane & 7;
    const int tg = (lane >> 3) & 3;
    const int t0 = wid * 16 + tg * 4;

    float accT[8][4];
    uint64_t accF[4][4];
#pragma unroll
    for (int nt = 0; nt < 8; ++nt)
#pragma unroll
        for (int q = 0; q < 4; ++q) accT[nt][q] = 0.0f;
#pragma unroll
    for (int p = 0; p < 4; ++p)
#pragma unroll
        for (int t = 0; t < 4; ++t) accF[p][t] = 0ull;

    float4 xa[4];   // tensor X staging: 128 tok x 32 k = 1024 float4 / 256 thr

#define LDG_XT(ii)                                                              \
    {                                                                           \
        _Pragma("unroll")                                                       \
        for (int it = 0; it < 4; ++it) {                                        \
            int f = it * NT + tid;                                              \
            int row = f >> 3, q = f & 7;                                        \
            xa[it] = *(const float4*)(Xg + (size_t)row * HDIM + (ii) * KI + q * 4); \
        }                                                                       \
    }

#define CVT_XT(bufo)                                                            \
    {                                                                           \
        _Pragma("unroll")                                                       \
        for (int it = 0; it < 4; ++it) {                                        \
            int f = it * NT + tid;                                              \
            int row = f >> 3, q = f & 7;                                        \
            uint32_t h0, l0, h1, l1;                                            \
            splitpair(xa[it].x, xa[it].y, h0, l0);                              \
            splitpair(xa[it].z, xa[it].w, h1, l1);                              \
            char* base = smc + (bufo) + row * 80 + q * 8;                       \
            *(uint2*)(base + XH_OFF) = make_uint2(h0, h1);                      \
            *(uint2*)(base + XL_OFF) = make_uint2(l0, l1);                      \
        }                                                                       \
    }

#define CP_ALL(ii, bufo)                                                        \
    {                                                                           \
        const char* ws = (const char*)g_w3 + (size_t)(ii) * 10240;              \
        _Pragma("unroll")                                                       \
        for (int q = 0; q < 3; ++q) {                                           \
            int idx = q * NT + tid;                                             \
            if (idx < 640)                                                      \
                cpasync16(sbase + (bufo) + W3_OFF + idx * 16, ws + idx * 16);   \
        }                                                                       \
        const char* wf = (const char*)g_wf + (size_t)(ii) * 8192;               \
        _Pragma("unroll")                                                       \
        for (int q = 0; q < 2; ++q) {                                           \
            int idx = q * NT + tid;                                             \
            cpasync16(sbase + (bufo) + WF_OFF + idx * 16, wf + idx * 16);       \
        }                                                                       \
        /* fma X: 128 tok x 128B, direct cp.async into [t][136B] rows */        \
        _Pragma("unroll")                                                       \
        for (int q = 0; q < 8; ++q) {                                           \
            int idx = q * NT + tid;                                             \
            int t = idx >> 4, seg = idx & 15;                                   \
            cpasync8(sbase + (bufo) + XF_OFF + t * 136 + seg * 8,               \
                     (const char*)(Xg + (size_t)t * HDIM + (ii) * KI + KT) +    \
                         seg * 8);                                              \
        }                                                                       \
        CP_COMMIT();                                                            \
    }

    // ---- stage iteration 0 ----
    LDG_XT(0);
    CP_ALL(0, 0);
    CVT_XT(0);
    CP_WAIT0();
    __syncthreads();

    for (int i = 0; i < NIT; ++i) {
        const uint32_t bufR = (uint32_t)(i & 1) * BUFB;
        const uint32_t bufW = (uint32_t)((i + 1) & 1) * BUFB;
        const bool more = (i + 1 < NIT);

        if (more) {
            LDG_XT(i + 1);
            CP_ALL(i + 1, bufW);
        }

        // ---- tensor section: 2 ksteps x 4 np x 2 sub x 3 passes = 48 MMAs ----
#pragma unroll
        for (int ks = 0; ks < 2; ++ks) {
            const uint32_t ko = (uint32_t)(ks * 32);
            uint32_t Ah[4], Al[4];
            ldsm4(Ah, aH + bufR + ko);
            ldsm4(Al, aL + bufR + ko);
#pragma unroll
            for (int np = 0; np < 4; ++np) {
                uint32_t Bh[4], Bl[4];
                ldsm4(Bh, bH[np] + bufR + ko);
                ldsm4(Bl, bH[np] + bufR + ko + 5120);
#pragma unroll
                for (int sub = 0; sub < 2; ++sub) {
                    float* cc = accT[np * 2 + sub];
                    mma16816(cc, Ah, Bh[sub], Bh[2 + sub]);   // h*h
                    mma16816(cc, Ah, Bl[sub], Bl[2 + sub]);   // h*l
                    mma16816(cc, Al, Bh[sub], Bh[2 + sub]);   // l*h
                }
            }
        }

        // ---- fma section: 32 kk exact fp32 on the FMA pipe ----
        {
            const char* xf = smc + bufR + XF_OFF;
            const char* wf = smc + bufR + WF_OFF;
#pragma unroll
            for (int k4 = 0; k4 < 8; ++k4) {
                float xarr[4][4];
#pragma unroll
                for (int t = 0; t < 4; ++t) {
                    const char* xp = xf + (t0 + t) * 136 + k4 * 16;
                    float2 a = *(const float2*)(xp);
                    float2 b = *(const float2*)(xp + 8);
                    xarr[t][0] = a.x; xarr[t][1] = a.y;
                    xarr[t][2] = b.x; xarr[t][3] = b.y;
                }
#pragma unroll
                for (int u = 0; u < 4; ++u) {
                    const int kk = k4 * 4 + u;
                    uint64_t xd[4];
                    DUP2(xd[0], xarr[0][u]);
                    DUP2(xd[1], xarr[1][u]);
                    DUP2(xd[2], xarr[2][u]);
                    DUP2(xd[3], xarr[3][u]);
                    const char* wrow = wf + kk * 256 + eg * 32;
                    ulonglong2 wA = *(const ulonglong2*)(wrow);
                    ulonglong2 wB = *(const ulonglong2*)(wrow + 16);
#pragma unroll
                    for (int t = 0; t < 4; ++t) {
                        FMA2(accF[0][t], xd[t], wA.x);
                        FMA2(accF[1][t], xd[t], wA.y);
                        FMA2(accF[2][t], xd[t], wB.x);
                        FMA2(accF[3][t], xd[t], wB.y);
                    }
                }
            }
        }

        if (more) {
            CVT_XT(bufW);
            CP_WAIT0();
        }
        __syncthreads();
    }

    // ---- merge: tensor fragments write lg, then fma accs add in ----
    float* lg = (float*)smc;
    const int g = lane >> 2, tig = lane & 3;
#pragma unroll
    for (int nt = 0; nt < 8; ++nt) {
        int r0 = wid * 16 + g;
        int e0 = nt * 8 + tig * 2;
        lg[r0 * 66 + e0]           = accT[nt][0];
        lg[r0 * 66 + e0 + 1]       = accT[nt][1];
        lg[(r0 + 8) * 66 + e0]     = accT[nt][2];
        lg[(r0 + 8) * 66 + e0 + 1] = accT[nt][3];
    }
    __syncthreads();
#pragma unroll
    for (int p = 0; p < 4; ++p) {
        int e = eg * 8 + 2 * p;
#pragma unroll
        for (int t = 0; t < 4; ++t) {
            float lo, hi;
            UNPK2(lo, hi, accF[p][t]);
            lg[(t0 + t) * 66 + e]     += lo;
            lg[(t0 + t) * 66 + e + 1] += hi;
        }
    }
    __syncthreads();

    // ---- per-token softmax + top-4 + near-tie flag (threads 0..127) ----
    if (tid < BM) {
        const int t = tid;
        const float* row = lg + t * 66;
        float mx = row[0];
#pragma unroll 8
        for (int e = 1; e < NE; ++e) mx = fmaxf(mx, row[e]);
        float sum = 0.0f;
        float s1 = -3.4e38f, s2 = -3.4e38f, s3 = -3.4e38f, s4 = -3.4e38f;
        int i1 = 0, i2 = 0, i3 = 0, i4 = 0;
#pragma unroll 8
        for (int e = 0; e < NE; ++e) {
            float l = row[e];
            sum += expf(l - mx);
            if (l > s1)      { s4 = s3; i4 = i3; s3 = s2; i3 = i2; s2 = s1; i2 = i1; s1 = l; i1 = e; }
            else if (l > s2) { s4 = s3; i4 = i3; s3 = s2; i3 = i2; s2 = l; i2 = e; }
            else if (l > s3) { s4 = s3; i4 = i3; s3 = l; i3 = e; }
            else if (l > s4) { s4 = l; i4 = e; }
        }
        float inv = 1.0f / sum;
        int gt = tok0 + t;
        out[2 * gt]               = (float)i1;
        out[2 * gt + 1]           = (float)i2;
        out[2 * TOK + 2 * gt]     = expf(s1 - mx) * inv;
        out[2 * TOK + 2 * gt + 1] = expf(s2 - mx) * inv;
        if ((s1 - s2 < TAU) || (s2 - s3 < TAU)) {
            int sl = atomicAdd(&g_flag_count, 1);
            if (sl < TOK) {
                g_flag_tok[sl] = gt;
                g_flag_pk[sl]  = (unsigned)i1 | ((unsigned)i2 << 8) |
                                 ((unsigned)i3 << 16) | ((unsigned)i4 << 24);
                g_flag_mx[sl]  = mx;
                g_flag_sum[sl] = sum;
            }
        }
    }
}

// ---------------- cleanup v3: fp64 recompute of the 4 candidate experts only ----
__global__ void cleanup3(const float* __restrict__ X, const float* __restrict__ W,
                         float* __restrict__ out) {
    __shared__ double red[128];
    __shared__ double lx[4];
    const int tid = threadIdx.x;
    int nf = g_flag_count;
    if (nf > TOK) nf = TOK;

    for (int j = blockIdx.x; j < nf; j += gridDim.x) {
        int t = g_flag_tok[j];
        unsigned pk = g_flag_pk[j];
        float mx = g_flag_mx[j];
        float inv = 1.0f / g_flag_sum[j];
        const float* xr = X + (size_t)t * HDIM;

        for (int q = 0; q < 4; ++q) {
            int e = (pk >> (8 * q)) & 0xFF;
            const float* wr = W + (size_t)e * HDIM;
            double a = 0.0;
            for (int k = tid; k < HDIM; k += 128)
                a += (double)xr[k] * (double)wr[k];
            red[tid] = a;
            __syncthreads();
            if (tid < 32) {
                double s = red[tid] + red[tid + 32] + red[tid + 64] + red[tid + 96];
#pragma unroll
                for (int off = 16; off > 0; off >>= 1)
                    s += __shfl_down_sync(0xFFFFFFFFu, s, off);
                if (tid == 0) lx[q] = s;
            }
            __syncthreads();
        }

        if (tid == 0) {
            int ids[4];
            double v[4];
#pragma unroll
            for (int q = 0; q < 4; ++q) {
                ids[q] = (pk >> (8 * q)) & 0xFF;
                v[q] = lx[q];
            }
            int b1 = 0;
#pragma unroll
            for (int q = 1; q < 4; ++q) if (v[q] > v[b1]) b1 = q;
            int b2 = (b1 == 0) ? 1 : 0;
#pragma unroll
            for (int q = 0; q < 4; ++q)
                if (q != b1 && v[q] > v[b2]) b2 = q;
            out[2 * t]     = (float)ids[b1];
            out[2 * t + 1] = (float)ids[b2];
            out[2 * TOK + 2 * t]     = expf((float)v[b1] - mx) * inv;
            out[2 * TOK + 2 * t + 1] = expf((float)v[b2] - mx) * inv;
        }
        __syncthreads();
    }
}

// ---------------- launch ----------------
extern "C" void kernel_launch(void* const* d_in, const int* in_sizes, int n_in,
                              void* d_out, int out_size) {
    const float* X = (const float*)d_in[0];
    const float* W = (const float*)d_in[1];
    float* out = (float*)d_out;

    static bool once = []() {
        cudaFuncSetAttribute(moe_gate_hybrid, cudaFuncAttributeMaxDynamicSharedMemorySize,
                             SMEMB);
        return true;
    }();
    (void)once;

    prep_w3<<<16, 256>>>(W);
    prep_wf<<<512, 256>>>(W);
    moe_gate_hybrid<<<TOK / BM, NT, SMEMB>>>(X, out);
    cleanup3<<<64, 128>>>(X, W, out);
}